// round 6
// baseline (speedup 1.0000x reference)
#include <cuda_runtime.h>
#include <stdint.h>

#define NN 50000
#define NE 640000
#define NG 256
#define HH 128
#define LL 4

// ---------------- scratch (device globals: allocation-free) ----------------
__device__ float g_h[NN * HH];                     // 25.6 MB (tf32-rounded at rest)
__device__ float g_e[(size_t)NE * HH];             // 327.7 MB (tf32-rounded at rest)
__device__ float g_agg[NN * HH];                   // 25.6 MB
__device__ float g_Wmr[LL * 3 * HH * HH];          // rounded weight copies
__device__ float g_Wer[LL * 3 * HH * HH];
__device__ float g_Whr[LL * 2 * HH * HH];

// ---------------- helpers ----------------
__device__ __forceinline__ uint32_t smem_to_u32(const void* p) {
    uint32_t a;
    asm("{ .reg .u64 t; cvta.to.shared.u64 t, %1; cvt.u32.u64 %0, t; }" : "=r"(a) : "l"(p));
    return a;
}
__device__ __forceinline__ float tf32r(float x) {   // round-to-nearest tf32 (zero-mean error)
    uint32_t u;
    asm("cvt.rna.tf32.f32 %0, %1;" : "=r"(u) : "f"(x));
    return __uint_as_float(u);
}
__device__ __forceinline__ void red2(float* p, float x, float y) {
    asm volatile("red.global.add.v2.f32 [%0], {%1,%2};" :: "l"(p), "f"(x), "f"(y) : "memory");
}
__device__ __forceinline__ void redv4(float* p, float4 v) {
    asm volatile("red.global.add.v4.f32 [%0], {%1,%2,%3,%4};"
                 :: "l"(p), "f"(v.x), "f"(v.y), "f"(v.z), "f"(v.w) : "memory");
}
__device__ __forceinline__ void cpa16(uint32_t dst, const void* src) {
    asm volatile("cp.async.cg.shared.global [%0], [%1], 16;" :: "r"(dst), "l"(src) : "memory");
}
#define CP_COMMIT() asm volatile("cp.async.commit_group;" ::: "memory")
#define CP_WAIT0()  asm volatile("cp.async.wait_group 0;" ::: "memory")
#define CP_WAIT1()  asm volatile("cp.async.wait_group 1;" ::: "memory")

// m16n8k8 tf32 HMMA (sm_80+; valid on plain sm_100 target)
__device__ __forceinline__ void mma8(float* d, const uint32_t* a, uint32_t b0, uint32_t b1) {
    asm volatile("mma.sync.aligned.m16n8k8.row.col.f32.tf32.tf32.f32 "
                 "{%0,%1,%2,%3}, {%4,%5,%6,%7}, {%8,%9}, {%0,%1,%2,%3};"
                 : "+f"(d[0]), "+f"(d[1]), "+f"(d[2]), "+f"(d[3])
                 : "r"(a[0]), "r"(a[1]), "r"(a[2]), "r"(a[3]), "r"(b0), "r"(b1));
}

// ---------------- small utility kernels ----------------
__global__ void zero_out_kernel(float* out) {
    out[blockIdx.x * blockDim.x + threadIdx.x] = 0.0f;
}
__global__ void zero_agg_kernel() {
    int i = blockIdx.x * blockDim.x + threadIdx.x;
    reinterpret_cast<float4*>(g_agg)[i] = make_float4(0.f, 0.f, 0.f, 0.f);
}
__global__ void round_agg_kernel() {
    int i = blockIdx.x * blockDim.x + threadIdx.x;
    float4 v = reinterpret_cast<float4*>(g_agg)[i];
    v.x = tf32r(v.x); v.y = tf32r(v.y); v.z = tf32r(v.z); v.w = tf32r(v.w);
    reinterpret_cast<float4*>(g_agg)[i] = v;
}
__global__ void round_weights_kernel(const float* __restrict__ Wm, const float* __restrict__ We,
                                     const float* __restrict__ Wh) {
    int i = blockIdx.x * blockDim.x + threadIdx.x;   // grid covers 196608
    g_Wmr[i] = tf32r(Wm[i]);
    g_Wer[i] = tf32r(We[i]);
    if (i < LL * 2 * HH * HH) g_Whr[i] = tf32r(Wh[i]);
}

// ---------------- embeddings (FFMA; tiny) — write tf32-rounded results ----------------
__global__ void embed_nodes_kernel(const float* __restrict__ x, const float* __restrict__ p,
                                   const float* __restrict__ W, const float* __restrict__ b) {
    __shared__ float Ws[80 * HH];
    __shared__ float As[16][81];
    int tid = threadIdx.x;
    for (int i = tid; i < 80 * HH; i += 128) Ws[i] = W[i];
    float bias = b[tid];
    __syncthreads();
    for (int chunk = blockIdx.x; chunk < NN / 16; chunk += gridDim.x) {
        int n0 = chunk * 16;
        __syncthreads();
        for (int i = tid; i < 16 * 64; i += 128) { int r = i >> 6, c = i & 63; As[r][c]      = x[(n0 + r) * 64 + c]; }
        for (int i = tid; i < 16 * 16; i += 128) { int r = i >> 4, c = i & 15; As[r][64 + c] = p[(n0 + r) * 16 + c]; }
        __syncthreads();
        #pragma unroll 4
        for (int r = 0; r < 16; r++) {
            float acc = bias;
            #pragma unroll
            for (int k = 0; k < 80; k++) acc += As[r][k] * Ws[k * HH + tid];
            g_h[(n0 + r) * HH + tid] = tf32r(acc);
        }
    }
}
__global__ void embed_edges_kernel(const float* __restrict__ ea,
                                   const float* __restrict__ W, const float* __restrict__ b) {
    __shared__ float Ws[16 * HH];
    __shared__ float As[32][17];
    int tid = threadIdx.x;
    for (int i = tid; i < 16 * HH; i += 128) Ws[i] = W[i];
    float bias = b[tid];
    __syncthreads();
    for (int chunk = blockIdx.x; chunk < NE / 32; chunk += gridDim.x) {
        int e0 = chunk * 32;
        __syncthreads();
        for (int i = tid; i < 32 * 16; i += 128) { int r = i >> 4, c = i & 15; As[r][c] = ea[(e0 + r) * 16 + c]; }
        __syncthreads();
        #pragma unroll 4
        for (int r = 0; r < 32; r++) {
            float acc = bias;
            #pragma unroll
            for (int k = 0; k < 16; k++) acc += As[r][k] * Ws[k * HH + tid];
            g_e[(size_t)(e0 + r) * HH + tid] = tf32r(acc);
        }
    }
}

// ================= EDGE kernel (fused Wm+We, mma.sync tf32, 3-stage cp.async) =================
// One CTA: 128 edges x 256 cols ([Wm | We]), K=384 in 12 chunks of 32.
// 512 threads = 16 warps as 4(M) x 4(N); warp tile 32x64; frags 2(M) x 8(N).
// SMEM ring (3 stages): A 3 x 18432 B (128 rows x 144 B); B 3 x 33792 B (32 rows x 1056 B).
// rowS @156672, rowR @157184. Total 157696 B.
#define E_SMEM 157696
__global__ __launch_bounds__(512)
void edge_kernel_mma(const int* __restrict__ send, const int* __restrict__ rec,
                     int l, const float* __restrict__ bm_l, const float* __restrict__ be_l) {
    extern __shared__ char sm[];
    const uint32_t smb = smem_to_u32(sm);
    const int tid = threadIdx.x, warp = tid >> 5, lane = tid & 31;
    const int g = lane >> 2, t = lane & 3;
    const int warpM = warp >> 2, warpN = warp & 3;
    const int e0 = blockIdx.x * 128;

    const float* Wm = g_Wmr + (size_t)l * 3 * HH * HH;
    const float* We = g_Wer + (size_t)l * 3 * HH * HH;

    int* rowSs = (int*)(sm + 156672);
    int* rowRs = (int*)(sm + 157184);
    if (tid < 128) {
        rowSs[tid] = send[e0 + tid] * HH;
        rowRs[tid] = rec [e0 + tid] * HH;
    }
    __syncthreads();

    auto issueA = [&](int c, int s) {
        const int region = c >> 2, koff = (c * 32) & 127;
        const uint32_t base = smb + s * 18432;
        #pragma unroll
        for (int i = 0; i < 2; i++) {
            int idx = tid + i * 512;
            int row = idx >> 3, q = idx & 7;
            const float* src;
            if (region == 0)      src = g_h + rowSs[row] + koff + q * 4;
            else if (region == 1) src = g_h + rowRs[row] + koff + q * 4;
            else                  src = g_e + (size_t)(e0 + row) * HH + koff + q * 4;
            cpa16(base + row * 144 + q * 16, src);
        }
    };
    auto issueB = [&](int c, int s) {
        const int k0 = c * 32;
        const uint32_t base = smb + 55296 + s * 33792;
        #pragma unroll
        for (int i = 0; i < 4; i++) {
            int idx = tid + i * 512;
            int k = idx >> 6, m = idx & 63;   // m: 64 x 16B segments across 256 cols
            const float* src = (m < 32) ? (Wm + (size_t)(k0 + k) * HH + m * 4)
                                        : (We + (size_t)(k0 + k) * HH + (m - 32) * 4);
            cpa16(base + k * 1056 + m * 16, src);
        }
    };

    float acc[2][8][4];
    #pragma unroll
    for (int mf = 0; mf < 2; mf++)
        #pragma unroll
        for (int nf = 0; nf < 8; nf++)
            #pragma unroll
            for (int r = 0; r < 4; r++) acc[mf][nf][r] = 0.f;

    issueA(0, 0); issueB(0, 0); CP_COMMIT();
    issueA(1, 1); issueB(1, 1); CP_COMMIT();

    for (int c = 0; c < 12; c++) {
        if (c + 1 < 12) CP_WAIT1(); else CP_WAIT0();   // group c complete
        __syncthreads();                               // also: all warps done with stage (c-1)%3
        if (c + 2 < 12) { issueA(c + 2, (c + 2) % 3); issueB(c + 2, (c + 2) % 3); CP_COMMIT(); }
        const int s = c % 3;
        const uint32_t* A32 = (const uint32_t*)(sm + s * 18432);
        const uint32_t* B32 = (const uint32_t*)(sm + 55296 + s * 33792);
        #pragma unroll
        for (int ks = 0; ks < 4; ks++) {
            uint32_t a[2][4];
            #pragma unroll
            for (int mf = 0; mf < 2; mf++) {
                const int r = warpM * 32 + mf * 16 + g;
                const uint32_t* ap = A32 + r * 36 + ks * 8 + t;
                a[mf][0] = ap[0];
                a[mf][1] = ap[8 * 36];
                a[mf][2] = ap[4];
                a[mf][3] = ap[8 * 36 + 4];
            }
            #pragma unroll
            for (int nf = 0; nf < 8; nf++) {
                const int n = warpN * 64 + nf * 8 + g;
                uint32_t b0 = B32[(ks * 8 + t) * 264 + n];
                uint32_t b1 = B32[(ks * 8 + t + 4) * 264 + n];
                mma8(acc[0][nf], a[0], b0, b1);
                mma8(acc[1][nf], a[1], b0, b1);
            }
        }
    }

    // ---- epilogue: warpN 0-1 -> messages (cols 0-127, scatter-add); warpN 2-3 -> e update ----
    if (warpN < 2) {
        #pragma unroll
        for (int mf = 0; mf < 2; mf++) {
            const int r0 = warpM * 32 + mf * 16 + g;
            float* d0 = g_agg + rowRs[r0];
            float* dU = g_agg + rowRs[r0 + 8];
            #pragma unroll
            for (int nf = 0; nf < 8; nf++) {
                const int col = warpN * 64 + nf * 8 + 2 * t;
                const float bx = bm_l[col], by = bm_l[col + 1];
                red2(d0 + col, acc[mf][nf][0] + bx, acc[mf][nf][1] + by);
                red2(dU + col, acc[mf][nf][2] + bx, acc[mf][nf][3] + by);
            }
        }
    } else {
        #pragma unroll
        for (int mf = 0; mf < 2; mf++) {
            const int r0 = warpM * 32 + mf * 16 + g;
            float* p0 = g_e + (size_t)(e0 + r0) * HH;        // in-place safe: all e reads done
            float* pU = g_e + (size_t)(e0 + r0 + 8) * HH;
            #pragma unroll
            for (int nf = 0; nf < 8; nf++) {
                const int col = (warpN - 2) * 64 + nf * 8 + 2 * t;
                const float bx = be_l[col], by = be_l[col + 1];
                *(float2*)(p0 + col) = make_float2(tf32r(acc[mf][nf][0] + bx), tf32r(acc[mf][nf][1] + by));
                *(float2*)(pU + col) = make_float2(tf32r(acc[mf][nf][2] + bx), tf32r(acc[mf][nf][3] + by));
            }
        }
    }
}

// ================= NODE kernel (mma.sync tf32, 3-stage) =================
// CTA: 128 nodes x 128 cols, K=256 ([h | agg]) in 8 chunks of 32.
// 256 threads = 8 warps as 4(M) x 2(N); warp tile 32x64.
// SMEM: A 3 x 18432; B 3 x 17408 (32 x 544 B). Total 107520.
#define N_SMEM 107520
__global__ __launch_bounds__(256)
void node_kernel_mma(int l, const float* __restrict__ bh_l) {
    extern __shared__ char sm[];
    const uint32_t smb = smem_to_u32(sm);
    const int tid = threadIdx.x, warp = tid >> 5, lane = tid & 31;
    const int g = lane >> 2, t = lane & 3;
    const int warpM = warp >> 1, warpN = warp & 1;
    const int n0 = blockIdx.x * 128;
    const float* W = g_Whr + (size_t)l * 2 * HH * HH;

    auto issueA = [&](int c, int s) {
        const float* srcb = (c < 4) ? g_h : g_agg;
        const int koff = (c * 32) & 127;
        const uint32_t base = smb + s * 18432;
        #pragma unroll
        for (int i = 0; i < 4; i++) {
            int idx = tid + i * 256;
            int row = idx >> 3, q = idx & 7;
            int n = n0 + row; if (n >= NN) n = NN - 1;      // clamp; writes guarded later
            cpa16(base + row * 144 + q * 16, srcb + (size_t)n * HH + koff + q * 4);
        }
    };
    auto issueB = [&](int c, int s) {
        const int k0 = c * 32;
        const uint32_t base = smb + 55296 + s * 17408;
        #pragma unroll
        for (int i = 0; i < 4; i++) {
            int idx = tid + i * 256;
            int k = idx >> 5, m = idx & 31;
            cpa16(base + k * 544 + m * 16, W + (size_t)(k0 + k) * HH + m * 4);
        }
    };

    float acc[2][8][4];
    #pragma unroll
    for (int mf = 0; mf < 2; mf++)
        #pragma unroll
        for (int nf = 0; nf < 8; nf++)
            #pragma unroll
            for (int r = 0; r < 4; r++) acc[mf][nf][r] = 0.f;

    issueA(0, 0); issueB(0, 0); CP_COMMIT();
    issueA(1, 1); issueB(1, 1); CP_COMMIT();

    for (int c = 0; c < 8; c++) {
        if (c + 1 < 8) CP_WAIT1(); else CP_WAIT0();
        __syncthreads();
        if (c + 2 < 8) { issueA(c + 2, (c + 2) % 3); issueB(c + 2, (c + 2) % 3); CP_COMMIT(); }
        const int s = c % 3;
        const uint32_t* A32 = (const uint32_t*)(sm + s * 18432);
        const uint32_t* B32 = (const uint32_t*)(sm + 55296 + s * 17408);
        #pragma unroll
        for (int ks = 0; ks < 4; ks++) {
            uint32_t a[2][4];
            #pragma unroll
            for (int mf = 0; mf < 2; mf++) {
                const int r = warpM * 32 + mf * 16 + g;
                const uint32_t* ap = A32 + r * 36 + ks * 8 + t;
                a[mf][0] = ap[0];
                a[mf][1] = ap[8 * 36];
                a[mf][2] = ap[4];
                a[mf][3] = ap[8 * 36 + 4];
            }
            #pragma unroll
            for (int nf = 0; nf < 8; nf++) {
                const int n = warpN * 64 + nf * 8 + g;
                uint32_t b0 = B32[(ks * 8 + t) * 136 + n];
                uint32_t b1 = B32[(ks * 8 + t + 4) * 136 + n];
                mma8(acc[0][nf], a[0], b0, b1);
                mma8(acc[1][nf], a[1], b0, b1);
            }
        }
    }

    // epilogue: in-place h update (CTA owns its rows; all h reads completed)
    #pragma unroll
    for (int mf = 0; mf < 2; mf++) {
        const int r0 = warpM * 32 + mf * 16 + g;
        const int nA = n0 + r0, nB = n0 + r0 + 8;
        #pragma unroll
        for (int nf = 0; nf < 8; nf++) {
            const int col = warpN * 64 + nf * 8 + 2 * t;
            const float bx = bh_l[col], by = bh_l[col + 1];
            if (nA < NN)
                *(float2*)(g_h + (size_t)nA * HH + col) =
                    make_float2(tf32r(acc[mf][nf][0] + bx), tf32r(acc[mf][nf][1] + by));
            if (nB < NN)
                *(float2*)(g_h + (size_t)nB * HH + col) =
                    make_float2(tf32r(acc[mf][nf][2] + bx), tf32r(acc[mf][nf][3] + by));
        }
    }
}

// ---------------- global add pool ----------------
__global__ void pool_kernel(const int* __restrict__ batch, float* __restrict__ out) {
    int gidx = blockIdx.x * blockDim.x + threadIdx.x;
    int n = gidx >> 5, lane = gidx & 31;
    if (n >= NN) return;
    int gr = batch[n];
    float4 v = reinterpret_cast<const float4*>(g_h + (size_t)n * HH)[lane];
    redv4(out + gr * HH + lane * 4, v);
}

// ---------------- launch ----------------
extern "C" void kernel_launch(void* const* d_in, const int* in_sizes, int n_in,
                              void* d_out, int out_size) {
    const float *x = 0, *p = 0, *e_attr = 0, *W_embed = 0, *b_embed = 0, *W_eembed = 0, *b_eembed = 0;
    const float *Wm = 0, *bm = 0, *Wh = 0, *bh = 0, *We = 0, *be = 0;
    const int *edge_index = 0, *batch = 0;
    int n128 = 0, n512 = 0, n196k = 0;
    for (int i = 0; i < n_in; i++) {
        long s = in_sizes[i];
        const void* ptr = d_in[i];
        switch (s) {
            case 3200000:  x          = (const float*)ptr; break;
            case 800000:   p          = (const float*)ptr; break;
            case 10240000: e_attr     = (const float*)ptr; break;
            case 1280000:  edge_index = (const int*)ptr;   break;
            case 50000:    batch      = (const int*)ptr;   break;
            case 10240:    W_embed    = (const float*)ptr; break;
            case 2048:     W_eembed   = (const float*)ptr; break;
            case 131072:   Wh         = (const float*)ptr; break;
            case 128:  if (n128++ == 0) b_embed = (const float*)ptr; else b_eembed = (const float*)ptr; break;
            case 196608: if (n196k++ == 0) Wm = (const float*)ptr; else We = (const float*)ptr; break;
            case 512:
                if (n512 == 0) bm = (const float*)ptr;
                else if (n512 == 1) bh = (const float*)ptr;
                else be = (const float*)ptr;
                n512++;
                break;
            default: break;
        }
    }

    cudaFuncSetAttribute(edge_kernel_mma, cudaFuncAttributeMaxDynamicSharedMemorySize, E_SMEM);
    cudaFuncSetAttribute(node_kernel_mma, cudaFuncAttributeMaxDynamicSharedMemorySize, N_SMEM);

    const int* send = edge_index;
    const int* rec  = edge_index + NE;
    float* out = (float*)d_out;

    round_weights_kernel<<<(LL * 3 * HH * HH) / 256, 256>>>(Wm, We, Wh);
    zero_out_kernel<<<(NG * HH) / 256, 256>>>(out);
    embed_nodes_kernel<<<1024, 128>>>(x, p, W_embed, b_embed);
    embed_edges_kernel<<<2048, 128>>>(e_attr, W_eembed, b_eembed);

    for (int l = 0; l < LL; l++) {
        zero_agg_kernel<<<(NN * HH / 4) / 256, 256>>>();
        edge_kernel_mma<<<NE / 128, 512, E_SMEM>>>(send, rec, l, bm + l * HH, be + l * HH);
        round_agg_kernel<<<(NN * HH / 4) / 256, 256>>>();
        node_kernel_mma<<<(NN + 127) / 128, 256, N_SMEM>>>(l, bh + l * HH);
    }

    pool_kernel<<<(NN * 32 + 255) / 256, 256>>>(batch, out);
}

// round 7
// speedup vs baseline: 1.4326x; 1.4326x over previous
#include <cuda_runtime.h>
#include <stdint.h>

#define NN 50000
#define NE 640000
#define NG 256
#define HH 128
#define LL 4

// ---------------- scratch (device globals: allocation-free) ----------------
__device__ float g_h[NN * HH];                     // 25.6 MB (tf32-rounded at rest)
__device__ float g_eA[(size_t)NE * HH];            // 327.7 MB (ping)
__device__ float g_eB[(size_t)NE * HH];            // 327.7 MB (pong)
__device__ float g_agg[NN * HH];                   // 25.6 MB
__device__ float g_P[(size_t)NN * 512];            // 102.4 MB: [U1|U2|V1|V2] per node
__device__ int   g_indeg[NN];
__device__ float g_Wmr[LL * 3 * HH * HH];          // tf32-rounded weight copies
__device__ float g_Wer[LL * 3 * HH * HH];
__device__ float g_Whr[LL * 2 * HH * HH];

// ---------------- helpers ----------------
__device__ __forceinline__ uint32_t smem_to_u32(const void* p) {
    uint32_t a;
    asm("{ .reg .u64 t; cvta.to.shared.u64 t, %1; cvt.u32.u64 %0, t; }" : "=r"(a) : "l"(p));
    return a;
}
__device__ __forceinline__ float tf32r(float x) {   // round-to-nearest tf32 (zero-mean error)
    uint32_t u;
    asm("cvt.rna.tf32.f32 %0, %1;" : "=r"(u) : "f"(x));
    return __uint_as_float(u);
}
__device__ __forceinline__ void red2(float* p, float x, float y) {
    asm volatile("red.global.add.v2.f32 [%0], {%1,%2};" :: "l"(p), "f"(x), "f"(y) : "memory");
}
__device__ __forceinline__ void redv4(float* p, float4 v) {
    asm volatile("red.global.add.v4.f32 [%0], {%1,%2,%3,%4};"
                 :: "l"(p), "f"(v.x), "f"(v.y), "f"(v.z), "f"(v.w) : "memory");
}
__device__ __forceinline__ void cpa16(uint32_t dst, const void* src) {
    asm volatile("cp.async.cg.shared.global [%0], [%1], 16;" :: "r"(dst), "l"(src) : "memory");
}
#define CP_COMMIT() asm volatile("cp.async.commit_group;" ::: "memory")
#define CP_WAIT0()  asm volatile("cp.async.wait_group 0;" ::: "memory")

// m16n8k8 tf32 HMMA (sm_80+; valid on plain sm_100 target)
__device__ __forceinline__ void mma8(float* d, const uint32_t* a, uint32_t b0, uint32_t b1) {
    asm volatile("mma.sync.aligned.m16n8k8.row.col.f32.tf32.tf32.f32 "
                 "{%0,%1,%2,%3}, {%4,%5,%6,%7}, {%8,%9}, {%0,%1,%2,%3};"
                 : "+f"(d[0]), "+f"(d[1]), "+f"(d[2]), "+f"(d[3])
                 : "r"(a[0]), "r"(a[1]), "r"(a[2]), "r"(a[3]), "r"(b0), "r"(b1));
}

// ---------------- small utility kernels ----------------
__global__ void zero_out_kernel(float* out) {
    out[blockIdx.x * blockDim.x + threadIdx.x] = 0.0f;
}
__global__ void zero_indeg_kernel() {
    int i = blockIdx.x * blockDim.x + threadIdx.x;
    if (i < NN) g_indeg[i] = 0;
}
__global__ void indeg_kernel(const int* __restrict__ rec) {
    int i = blockIdx.x * blockDim.x + threadIdx.x;   // grid covers NE exactly
    atomicAdd(&g_indeg[rec[i]], 1);
}
// agg[n][c] = indeg[n] * (U2[n][c] + bm[c])   (folds the h_rec@Wm2 + bm term)
__global__ void agg_init_kernel(const float* __restrict__ bm_l) {
    int i = blockIdx.x * blockDim.x + threadIdx.x;   // NN*HH/4 elements
    int n = i >> 5, c4 = (i & 31) * 4;
    float cnt = (float)g_indeg[n];
    float4 u = *(const float4*)(g_P + (size_t)n * 512 + 128 + c4);
    float4 b = *(const float4*)(bm_l + c4);
    reinterpret_cast<float4*>(g_agg)[i] =
        make_float4(cnt * (u.x + b.x), cnt * (u.y + b.y), cnt * (u.z + b.z), cnt * (u.w + b.w));
}
__global__ void round_agg_kernel() {
    int i = blockIdx.x * blockDim.x + threadIdx.x;
    float4 v = reinterpret_cast<float4*>(g_agg)[i];
    v.x = tf32r(v.x); v.y = tf32r(v.y); v.z = tf32r(v.z); v.w = tf32r(v.w);
    reinterpret_cast<float4*>(g_agg)[i] = v;
}
__global__ void round_weights_kernel(const float* __restrict__ Wm, const float* __restrict__ We,
                                     const float* __restrict__ Wh) {
    int i = blockIdx.x * blockDim.x + threadIdx.x;   // grid covers 196608
    g_Wmr[i] = tf32r(Wm[i]);
    g_Wer[i] = tf32r(We[i]);
    if (i < LL * 2 * HH * HH) g_Whr[i] = tf32r(Wh[i]);
}

// ---------------- embeddings (FFMA; tiny) — write tf32-rounded results ----------------
__global__ void embed_nodes_kernel(const float* __restrict__ x, const float* __restrict__ p,
                                   const float* __restrict__ W, const float* __restrict__ b) {
    __shared__ float Ws[80 * HH];
    __shared__ float As[16][81];
    int tid = threadIdx.x;
    for (int i = tid; i < 80 * HH; i += 128) Ws[i] = W[i];
    float bias = b[tid];
    __syncthreads();
    for (int chunk = blockIdx.x; chunk < NN / 16; chunk += gridDim.x) {
        int n0 = chunk * 16;
        __syncthreads();
        for (int i = tid; i < 16 * 64; i += 128) { int r = i >> 6, c = i & 63; As[r][c]      = x[(n0 + r) * 64 + c]; }
        for (int i = tid; i < 16 * 16; i += 128) { int r = i >> 4, c = i & 15; As[r][64 + c] = p[(n0 + r) * 16 + c]; }
        __syncthreads();
        #pragma unroll 4
        for (int r = 0; r < 16; r++) {
            float acc = bias;
            #pragma unroll
            for (int k = 0; k < 80; k++) acc += As[r][k] * Ws[k * HH + tid];
            g_h[(n0 + r) * HH + tid] = tf32r(acc);
        }
    }
}
__global__ void embed_edges_kernel(const float* __restrict__ ea,
                                   const float* __restrict__ W, const float* __restrict__ b) {
    __shared__ float Ws[16 * HH];
    __shared__ float As[32][17];
    int tid = threadIdx.x;
    for (int i = tid; i < 16 * HH; i += 128) Ws[i] = W[i];
    float bias = b[tid];
    __syncthreads();
    for (int chunk = blockIdx.x; chunk < NE / 32; chunk += gridDim.x) {
        int e0 = chunk * 32;
        __syncthreads();
        for (int i = tid; i < 32 * 16; i += 128) { int r = i >> 4, c = i & 15; As[r][c] = ea[(e0 + r) * 16 + c]; }
        __syncthreads();
        #pragma unroll 4
        for (int r = 0; r < 32; r++) {
            float acc = bias;
            #pragma unroll
            for (int k = 0; k < 16; k++) acc += As[r][k] * Ws[k * HH + tid];
            g_eA[(size_t)(e0 + r) * HH + tid] = tf32r(acc);
        }
    }
}

// ================= PRECOMPUTE kernel: P = h @ [Wm1|Wm2|We1|We2] =================
// grid (391, 4): y selects the 128x128 weight block / output quarter. CTA tile 128x128, K=128.
// 256 thr, 8 warps 4(M)x2(N), warp 32x64, 2-stage cp.async. SMEM: A 2x18432 + B 2x17408 = 71680.
#define P_SMEM 71680
__global__ __launch_bounds__(256)
void precompute_P_kernel(int l) {
    extern __shared__ char sm[];
    const uint32_t smb = smem_to_u32(sm);
    const int tid = threadIdx.x, warp = tid >> 5, lane = tid & 31;
    const int g = lane >> 2, t = lane & 3;
    const int warpM = warp >> 1, warpN = warp & 1;
    const int n0 = blockIdx.x * 128;
    const int yy = blockIdx.y;
    const float* W = ((yy < 2) ? g_Wmr : g_Wer) + (size_t)l * 3 * HH * HH + (size_t)(yy & 1) * HH * HH;

    auto issueA = [&](int c, int s) {
        const uint32_t base = smb + s * 18432;
        #pragma unroll
        for (int i = 0; i < 4; i++) {
            int idx = tid + i * 256;
            int row = idx >> 3, q = idx & 7;
            int n = n0 + row; if (n >= NN) n = NN - 1;
            cpa16(base + row * 144 + q * 16, g_h + (size_t)n * HH + c * 32 + q * 4);
        }
    };
    auto issueB = [&](int c, int s) {
        const uint32_t base = smb + 36864 + s * 17408;
        #pragma unroll
        for (int i = 0; i < 4; i++) {
            int idx = tid + i * 256;
            int k = idx >> 5, m = idx & 31;
            cpa16(base + k * 544 + m * 16, W + (size_t)(c * 32 + k) * HH + m * 4);
        }
    };

    float acc[2][8][4];
    #pragma unroll
    for (int mf = 0; mf < 2; mf++)
        #pragma unroll
        for (int nf = 0; nf < 8; nf++)
            #pragma unroll
            for (int r = 0; r < 4; r++) acc[mf][nf][r] = 0.f;

    issueA(0, 0); issueB(0, 0); CP_COMMIT();
    for (int c = 0; c < 4; c++) {
        CP_WAIT0();
        __syncthreads();
        if (c + 1 < 4) { issueA(c + 1, (c + 1) & 1); issueB(c + 1, (c + 1) & 1); CP_COMMIT(); }
        const int s = c & 1;
        const uint32_t* A32 = (const uint32_t*)(sm + s * 18432);
        const uint32_t* B32 = (const uint32_t*)(sm + 36864 + s * 17408);
        #pragma unroll
        for (int ks = 0; ks < 4; ks++) {
            uint32_t a[2][4];
            #pragma unroll
            for (int mf = 0; mf < 2; mf++) {
                const int r = warpM * 32 + mf * 16 + g;
                const uint32_t* ap = A32 + r * 36 + ks * 8 + t;
                a[mf][0] = ap[0]; a[mf][1] = ap[8 * 36]; a[mf][2] = ap[4]; a[mf][3] = ap[8 * 36 + 4];
            }
            #pragma unroll
            for (int nf = 0; nf < 8; nf++) {
                const int n = warpN * 64 + nf * 8 + g;
                uint32_t b0 = B32[(ks * 8 + t) * 136 + n];
                uint32_t b1 = B32[(ks * 8 + t + 4) * 136 + n];
                mma8(acc[0][nf], a[0], b0, b1);
                mma8(acc[1][nf], a[1], b0, b1);
            }
        }
        __syncthreads();
    }

    // store fp32 (epilogue addends, not MMA inputs -> no rounding)
    #pragma unroll
    for (int mf = 0; mf < 2; mf++) {
        const int r0 = warpM * 32 + mf * 16 + g;
        const int nA = n0 + r0, nB = n0 + r0 + 8;
        #pragma unroll
        for (int nf = 0; nf < 8; nf++) {
            const int col = yy * 128 + warpN * 64 + nf * 8 + 2 * t;
            if (nA < NN) *(float2*)(g_P + (size_t)nA * 512 + col) = make_float2(acc[mf][nf][0], acc[mf][nf][1]);
            if (nB < NN) *(float2*)(g_P + (size_t)nB * 512 + col) = make_float2(acc[mf][nf][2], acc[mf][nf][3]);
        }
    }
}

// ================= EDGE kernel v2: e @ [Wm3 or We3], K=128 only =================
// grid (5000, 2): y=0 -> messages (acc + U1[send] scatter-add to agg); y=1 -> e update
// (acc + V1[send] + V2[rec] + be -> e_out). A = streaming e rows (coalesced, no gather).
// 256 thr, 8 warps 4(M)x2(N), warp 32x64, 2-stage. SMEM 71680 + idx tables = 72704 -> 2 CTAs/SM.
#define E_SMEM 72704
__global__ __launch_bounds__(256)
void edge_kernel_v2(const int* __restrict__ send, const int* __restrict__ rec,
                    int l, int eflip, const float* __restrict__ be_l) {
    extern __shared__ char sm[];
    const uint32_t smb = smem_to_u32(sm);
    const int tid = threadIdx.x, warp = tid >> 5, lane = tid & 31;
    const int g = lane >> 2, t = lane & 3;
    const int warpM = warp >> 1, warpN = warp & 1;
    const int e0 = blockIdx.x * 128;
    const int yy = blockIdx.y;

    const float* W = (yy ? g_Wer : g_Wmr) + (size_t)l * 3 * HH * HH + (size_t)2 * HH * HH;  // rows 256:384
    const float* e_in  = eflip ? g_eB : g_eA;
    float*       e_out = eflip ? g_eA : g_eB;

    int* sIdx = (int*)(sm + 71680);
    int* rIdx = (int*)(sm + 72192);
    if (tid < 128) { sIdx[tid] = send[e0 + tid]; rIdx[tid] = rec[e0 + tid]; }

    auto issueA = [&](int c, int s) {
        const uint32_t base = smb + s * 18432;
        #pragma unroll
        for (int i = 0; i < 4; i++) {
            int idx = tid + i * 256;
            int row = idx >> 3, q = idx & 7;
            cpa16(base + row * 144 + q * 16, e_in + (size_t)(e0 + row) * HH + c * 32 + q * 4);
        }
    };
    auto issueB = [&](int c, int s) {
        const uint32_t base = smb + 36864 + s * 17408;
        #pragma unroll
        for (int i = 0; i < 4; i++) {
            int idx = tid + i * 256;
            int k = idx >> 5, m = idx & 31;
            cpa16(base + k * 544 + m * 16, W + (size_t)(c * 32 + k) * HH + m * 4);
        }
    };

    float acc[2][8][4];
    #pragma unroll
    for (int mf = 0; mf < 2; mf++)
        #pragma unroll
        for (int nf = 0; nf < 8; nf++)
            #pragma unroll
            for (int r = 0; r < 4; r++) acc[mf][nf][r] = 0.f;

    issueA(0, 0); issueB(0, 0); CP_COMMIT();
    for (int c = 0; c < 4; c++) {
        CP_WAIT0();
        __syncthreads();
        if (c + 1 < 4) { issueA(c + 1, (c + 1) & 1); issueB(c + 1, (c + 1) & 1); CP_COMMIT(); }
        const int s = c & 1;
        const uint32_t* A32 = (const uint32_t*)(sm + s * 18432);
        const uint32_t* B32 = (const uint32_t*)(sm + 36864 + s * 17408);
        #pragma unroll
        for (int ks = 0; ks < 4; ks++) {
            uint32_t a[2][4];
            #pragma unroll
            for (int mf = 0; mf < 2; mf++) {
                const int r = warpM * 32 + mf * 16 + g;
                const uint32_t* ap = A32 + r * 36 + ks * 8 + t;
                a[mf][0] = ap[0]; a[mf][1] = ap[8 * 36]; a[mf][2] = ap[4]; a[mf][3] = ap[8 * 36 + 4];
            }
            #pragma unroll
            for (int nf = 0; nf < 8; nf++) {
                const int n = warpN * 64 + nf * 8 + g;
                uint32_t b0 = B32[(ks * 8 + t) * 136 + n];
                uint32_t b1 = B32[(ks * 8 + t + 4) * 136 + n];
                mma8(acc[0][nf], a[0], b0, b1);
                mma8(acc[1][nf], a[1], b0, b1);
            }
        }
        __syncthreads();
    }

    if (yy == 0) {      // message = acc + U1[send]; scatter-add into agg[rec]
        #pragma unroll
        for (int mf = 0; mf < 2; mf++) {
            const int r0 = warpM * 32 + mf * 16 + g;
            const float* uA = g_P + (size_t)sIdx[r0] * 512;
            const float* uB = g_P + (size_t)sIdx[r0 + 8] * 512;
            float* dA = g_agg + (size_t)rIdx[r0] * HH;
            float* dB = g_agg + (size_t)rIdx[r0 + 8] * HH;
            #pragma unroll
            for (int nf = 0; nf < 8; nf++) {
                const int col = warpN * 64 + nf * 8 + 2 * t;
                float2 ua = *(const float2*)(uA + col);
                float2 ub = *(const float2*)(uB + col);
                red2(dA + col, acc[mf][nf][0] + ua.x, acc[mf][nf][1] + ua.y);
                red2(dB + col, acc[mf][nf][2] + ub.x, acc[mf][nf][3] + ub.y);
            }
        }
    } else {            // e_new = acc + V1[send] + V2[rec] + be  (tf32-rounded at rest)
        #pragma unroll
        for (int mf = 0; mf < 2; mf++) {
            const int r0 = warpM * 32 + mf * 16 + g;
            const float* v1A = g_P + (size_t)sIdx[r0] * 512 + 256;
            const float* v1B = g_P + (size_t)sIdx[r0 + 8] * 512 + 256;
            const float* v2A = g_P + (size_t)rIdx[r0] * 512 + 384;
            const float* v2B = g_P + (size_t)rIdx[r0 + 8] * 512 + 384;
            float* pA = e_out + (size_t)(e0 + r0) * HH;
            float* pB = e_out + (size_t)(e0 + r0 + 8) * HH;
            #pragma unroll
            for (int nf = 0; nf < 8; nf++) {
                const int col = warpN * 64 + nf * 8 + 2 * t;
                float2 a1 = *(const float2*)(v1A + col);
                float2 a2 = *(const float2*)(v2A + col);
                float2 b1 = *(const float2*)(v1B + col);
                float2 b2 = *(const float2*)(v2B + col);
                const float bx = be_l[col], by = be_l[col + 1];
                *(float2*)(pA + col) = make_float2(tf32r(acc[mf][nf][0] + a1.x + a2.x + bx),
                                                   tf32r(acc[mf][nf][1] + a1.y + a2.y + by));
                *(float2*)(pB + col) = make_float2(tf32r(acc[mf][nf][2] + b1.x + b2.x + bx),
                                                   tf32r(acc[mf][nf][3] + b1.y + b2.y + by));
            }
        }
    }
}

// ================= NODE kernel (mma.sync tf32, 2-stage; R5-proven) =================
#define N_SMEM 71680
__global__ __launch_bounds__(256)
void node_kernel_mma(int l, const float* __restrict__ bh_l) {
    extern __shared__ char sm[];
    const uint32_t smb = smem_to_u32(sm);
    const int tid = threadIdx.x, warp = tid >> 5, lane = tid & 31;
    const int g = lane >> 2, t = lane & 3;
    const int warpM = warp >> 1, warpN = warp & 1;
    const int n0 = blockIdx.x * 128;
    const float* W = g_Whr + (size_t)l * 2 * HH * HH;

    auto issueA = [&](int c, int s) {
        const float* srcb = (c < 4) ? g_h : g_agg;
        const int koff = (c * 32) & 127;
        const uint32_t base = smb + s * 18432;
        #pragma unroll
        for (int i = 0; i < 4; i++) {
            int idx = tid + i * 256;
            int row = idx >> 3, q = idx & 7;
            int n = n0 + row; if (n >= NN) n = NN - 1;
            cpa16(base + row * 144 + q * 16, srcb + (size_t)n * HH + koff + q * 4);
        }
    };
    auto issueB = [&](int c, int s) {
        const uint32_t base = smb + 36864 + s * 17408;
        #pragma unroll
        for (int i = 0; i < 4; i++) {
            int idx = tid + i * 256;
            int k = idx >> 5, m = idx & 31;
            cpa16(base + k * 544 + m * 16, W + (size_t)(c * 32 + k) * HH + m * 4);
        }
    };

    float acc[2][8][4];
    #pragma unroll
    for (int mf = 0; mf < 2; mf++)
        #pragma unroll
        for (int nf = 0; nf < 8; nf++)
            #pragma unroll
            for (int r = 0; r < 4; r++) acc[mf][nf][r] = 0.f;

    issueA(0, 0); issueB(0, 0); CP_COMMIT();
    for (int c = 0; c < 8; c++) {
        CP_WAIT0();
        __syncthreads();
        if (c + 1 < 8) { issueA(c + 1, (c + 1) & 1); issueB(c + 1, (c + 1) & 1); CP_COMMIT(); }
        const int s = c & 1;
        const uint32_t* A32 = (const uint32_t*)(sm + s * 18432);
        const uint32_t* B32 = (const uint32_t*)(sm + 36864 + s * 17408);
        #pragma unroll
        for (int ks = 0; ks < 4; ks++) {
            uint32_t a[2][4];
            #pragma unroll
            for (int mf = 0; mf < 2; mf++) {
                const int r = warpM * 32 + mf * 16 + g;
                const uint32_t* ap = A32 + r * 36 + ks * 8 + t;
                a[mf][0] = ap[0]; a[mf][1] = ap[8 * 36]; a[mf][2] = ap[4]; a[mf][3] = ap[8 * 36 + 4];
            }
            #pragma unroll
            for (int nf = 0; nf < 8; nf++) {
                const int n = warpN * 64 + nf * 8 + g;
                uint32_t b0 = B32[(ks * 8 + t) * 136 + n];
                uint32_t b1 = B32[(ks * 8 + t + 4) * 136 + n];
                mma8(acc[0][nf], a[0], b0, b1);
                mma8(acc[1][nf], a[1], b0, b1);
            }
        }
        __syncthreads();
    }

    #pragma unroll
    for (int mf = 0; mf < 2; mf++) {
        const int r0 = warpM * 32 + mf * 16 + g;
        const int nA = n0 + r0, nB = n0 + r0 + 8;
        #pragma unroll
        for (int nf = 0; nf < 8; nf++) {
            const int col = warpN * 64 + nf * 8 + 2 * t;
            const float bx = bh_l[col], by = bh_l[col + 1];
            if (nA < NN)
                *(float2*)(g_h + (size_t)nA * HH + col) =
                    make_float2(tf32r(acc[mf][nf][0] + bx), tf32r(acc[mf][nf][1] + by));
            if (nB < NN)
                *(float2*)(g_h + (size_t)nB * HH + col) =
                    make_float2(tf32r(acc[mf][nf][2] + bx), tf32r(acc[mf][nf][3] + by));
        }
    }
}

// ---------------- global add pool ----------------
__global__ void pool_kernel(const int* __restrict__ batch, float* __restrict__ out) {
    int gidx = blockIdx.x * blockDim.x + threadIdx.x;
    int n = gidx >> 5, lane = gidx & 31;
    if (n >= NN) return;
    int gr = batch[n];
    float4 v = reinterpret_cast<const float4*>(g_h + (size_t)n * HH)[lane];
    redv4(out + gr * HH + lane * 4, v);
}

// ---------------- launch ----------------
extern "C" void kernel_launch(void* const* d_in, const int* in_sizes, int n_in,
                              void* d_out, int out_size) {
    const float *x = 0, *p = 0, *e_attr = 0, *W_embed = 0, *b_embed = 0, *W_eembed = 0, *b_eembed = 0;
    const float *Wm = 0, *bm = 0, *Wh = 0, *bh = 0, *We = 0, *be = 0;
    const int *edge_index = 0, *batch = 0;
    int n128 = 0, n512 = 0, n196k = 0;
    for (int i = 0; i < n_in; i++) {
        long s = in_sizes[i];
        const void* ptr = d_in[i];
        switch (s) {
            case 3200000:  x          = (const float*)ptr; break;
            case 800000:   p          = (const float*)ptr; break;
            case 10240000: e_attr     = (const float*)ptr; break;
            case 1280000:  edge_index = (const int*)ptr;   break;
            case 50000:    batch      = (const int*)ptr;   break;
            case 10240:    W_embed    = (const float*)ptr; break;
            case 2048:     W_eembed   = (const float*)ptr; break;
            case 131072:   Wh         = (const float*)ptr; break;
            case 128:  if (n128++ == 0) b_embed = (const float*)ptr; else b_eembed = (const float*)ptr; break;
            case 196608: if (n196k++ == 0) Wm = (const float*)ptr; else We = (const float*)ptr; break;
            case 512:
                if (n512 == 0) bm = (const float*)ptr;
                else if (n512 == 1) bh = (const float*)ptr;
                else be = (const float*)ptr;
                n512++;
                break;
            default: break;
        }
    }

    cudaFuncSetAttribute(precompute_P_kernel, cudaFuncAttributeMaxDynamicSharedMemorySize, P_SMEM);
    cudaFuncSetAttribute(edge_kernel_v2,      cudaFuncAttributeMaxDynamicSharedMemorySize, E_SMEM);
    cudaFuncSetAttribute(node_kernel_mma,     cudaFuncAttributeMaxDynamicSharedMemorySize, N_SMEM);

    const int* send = edge_index;
    const int* rec  = edge_index + NE;
    float* out = (float*)d_out;

    round_weights_kernel<<<(LL * 3 * HH * HH) / 256, 256>>>(Wm, We, Wh);
    zero_out_kernel<<<(NG * HH) / 256, 256>>>(out);
    zero_indeg_kernel<<<(NN + 255) / 256, 256>>>();
    indeg_kernel<<<NE / 256, 256>>>(rec);
    embed_nodes_kernel<<<1024, 128>>>(x, p, W_embed, b_embed);
    embed_edges_kernel<<<2048, 128>>>(e_attr, W_eembed, b_eembed);

    for (int l = 0; l < LL; l++) {
        precompute_P_kernel<<<dim3((NN + 127) / 128, 4), 256, P_SMEM>>>(l);
        agg_init_kernel<<<(NN * HH / 4) / 256, 256>>>(bm + l * HH);
        edge_kernel_v2<<<dim3(NE / 128, 2), 256, E_SMEM>>>(send, rec, l, l & 1, be + l * HH);
        round_agg_kernel<<<(NN * HH / 4) / 256, 256>>>();
        node_kernel_mma<<<(NN + 127) / 128, 256, N_SMEM>>>(l, bh + l * HH);
    }

    pool_kernel<<<(NN * 32 + 255) / 256, 256>>>(batch, out);
}